// round 16
// baseline (speedup 1.0000x reference)
#include <cuda_runtime.h>
#include <cuda_fp16.h>
#include <math.h>
#include <stdint.h>

#define BATCH 8
#define NN    2048
#define FIN   256
#define FOUT  256
#define NEG_INF_F (-9000000000000000.0f)
#define ALPHA_F 0.2f

#define BI 64             // i-rows per attention block
#define BJ 64             // j-cols per tile (MMA K per tile; 4 x k=16 chunks)
#define NT (NN / BJ)      // 32 tiles
#define KPAD 72           // padded k-stride (elements): 144 B row, conflict-free ldsm

// Scratch (static device globals; no allocation anywhere)
__device__ __align__(16) float g_Wh[BATCH * NN * FOUT];        // 16.8 MB
__device__ __align__(16) __half g_WhT[BATCH * FOUT * NN];      // [b][n][j] fp16
__device__ float g_f1[BATCH * NN];
__device__ float g_f2[BATCH * NN];

// ---------------------------------------------------------------------------
// Helpers: ldmatrix + mma.sync + cp.async (sm_80-class PTX; valid at compute_103)
// ---------------------------------------------------------------------------
__device__ __forceinline__ uint32_t smem_u32(const void* p) {
    uint32_t a;
    asm("{ .reg .u64 t; cvta.to.shared.u64 t, %1; cvt.u32.u64 %0, t; }" : "=r"(a) : "l"(p));
    return a;
}
__device__ __forceinline__ void ldsm4(uint32_t& r0, uint32_t& r1, uint32_t& r2, uint32_t& r3,
                                      uint32_t addr) {
    asm volatile("ldmatrix.sync.aligned.m8n8.x4.shared.b16 {%0,%1,%2,%3}, [%4];"
                 : "=r"(r0), "=r"(r1), "=r"(r2), "=r"(r3) : "r"(addr));
}
__device__ __forceinline__ void mma16816h(float* c, uint32_t a0, uint32_t a1, uint32_t a2,
                                          uint32_t a3, uint32_t b0, uint32_t b1) {
    asm volatile(
        "mma.sync.aligned.m16n8k16.row.col.f32.f16.f16.f32 "
        "{%0,%1,%2,%3}, {%4,%5,%6,%7}, {%8,%9}, {%0,%1,%2,%3};"
        : "+f"(c[0]), "+f"(c[1]), "+f"(c[2]), "+f"(c[3])
        : "r"(a0), "r"(a1), "r"(a2), "r"(a3), "r"(b0), "r"(b1));
}
#define CP_ASYNC16(dst, src) \
    asm volatile("cp.async.cg.shared.global [%0], [%1], 16;" :: "r"(dst), "l"(src))
#define CP_COMMIT() asm volatile("cp.async.commit_group;" ::: "memory")
#define CP_WAIT0()  asm volatile("cp.async.wait_group 0;" ::: "memory")

// ---------------------------------------------------------------------------
// Kernel 1: Wh[row][o] = sum_f h[row][f] * W[o][f]  (unchanged; 68.7us, passes)
// ---------------------------------------------------------------------------
__global__ void __launch_bounds__(256) gemm_wh_kernel(const float* __restrict__ h,
                                                      const float* __restrict__ W) {
    __shared__ float hs[64][33];
    __shared__ float ws[64][33];

    const int row0 = blockIdx.y * 64;
    const int col0 = blockIdx.x * 64;
    const int tid = threadIdx.x;
    const int tx = tid & 15;
    const int ty = tid >> 4;

    float acc[4][4] = {};

    for (int k0 = 0; k0 < FIN; k0 += 32) {
        #pragma unroll
        for (int t = 0; t < 8; t++) {
            int idx = tid + t * 256;
            int r = idx >> 5, k = idx & 31;
            hs[r][k] = h[(size_t)(row0 + r) * FIN + k0 + k];
            ws[r][k] = W[(size_t)(col0 + r) * FIN + k0 + k];
        }
        __syncthreads();
        #pragma unroll
        for (int k = 0; k < 32; k++) {
            float av[4], bv[4];
            #pragma unroll
            for (int i = 0; i < 4; i++) av[i] = hs[ty * 4 + i][k];
            #pragma unroll
            for (int j = 0; j < 4; j++) bv[j] = ws[tx * 4 + j][k];
            #pragma unroll
            for (int i = 0; i < 4; i++)
                #pragma unroll
                for (int j = 0; j < 4; j++)
                    acc[i][j] = fmaf(av[i], bv[j], acc[i][j]);
        }
        __syncthreads();
    }

    #pragma unroll
    for (int i = 0; i < 4; i++) {
        float4 v = make_float4(acc[i][0], acc[i][1], acc[i][2], acc[i][3]);
        *(float4*)&g_Wh[(size_t)(row0 + ty * 4 + i) * FOUT + col0 + tx * 4] = v;
    }
}

// ---------------------------------------------------------------------------
// Kernel 1b: transpose + fp16 convert: g_Wh[b][j][n] -> g_WhT[b][n][j]
// ---------------------------------------------------------------------------
__global__ void __launch_bounds__(256) transp_kernel() {
    __shared__ float ts[64][65];
    const int b  = blockIdx.z;
    const int j0 = blockIdx.x * 64;
    const int n0 = blockIdx.y * 64;
    const int tid = threadIdx.x;

    #pragma unroll
    for (int it = 0; it < 16; it++) {
        int idx = tid + it * 256;
        int r = idx >> 6, c = idx & 63;
        ts[r][c] = g_Wh[((size_t)b * NN + j0 + r) * FOUT + n0 + c];
    }
    __syncthreads();

    const int tx = tid & 31;   // j-pair index (32 pairs of j)
    const int ty = tid >> 5;   // n base (8 per iter)
    #pragma unroll
    for (int it = 0; it < 8; it++) {
        int n = ty + it * 8;
        float w0 = ts[tx * 2 + 0][n];
        float w1 = ts[tx * 2 + 1][n];
        size_t off = ((size_t)b * FOUT + n0 + n) * NN + j0 + tx * 2;
        __half2 v; v.x = __float2half(w0); v.y = __float2half(w1);
        *(__half2*)&g_WhT[off] = v;
    }
}

// ---------------------------------------------------------------------------
// Kernel 2: f1/f2 (unchanged)
// ---------------------------------------------------------------------------
__global__ void __launch_bounds__(256) fvec_kernel(const float* __restrict__ a) {
    int gwarp = (blockIdx.x * blockDim.x + threadIdx.x) >> 5;
    int lane = threadIdx.x & 31;
    if (gwarp >= BATCH * NN) return;
    const float* wh = g_Wh + (size_t)gwarp * FOUT;
    float s1 = 0.f, s2 = 0.f;
    #pragma unroll
    for (int k = lane; k < FOUT; k += 32) {
        float v = wh[k];
        s1 = fmaf(v, a[k], s1);
        s2 = fmaf(v, a[FOUT + k], s2);
    }
    #pragma unroll
    for (int o = 16; o > 0; o >>= 1) {
        s1 += __shfl_xor_sync(0xffffffffu, s1, o);
        s2 += __shfl_xor_sync(0xffffffffu, s2, o);
    }
    if (lane == 0) { g_f1[gwarp] = s1; g_f2[gwarp] = s2; }
}

// ---------------------------------------------------------------------------
// Kernel 3: warp-MMA fused attention, fp16 single-term, cp.async pipeline.
// BJ=64: 32 tiles (was 64) -> half the barriers / pipeline turnarounds;
// per-tile MMA work doubles so cp.async latency hides fully under MMA.
// 8 warps as 2(M) x 4(N); warp tile 32x64; ONE __syncthreads per tile.
// Unnormalized accumulate (|e| <= ~7 -> P <= ~1100, no fp16 overflow);
// divide by fp32 l at the end. 2 CTAs/SM.
//
// smem (92416 B dynamic), buffer q in {0,1}:
//   B(q) = q*36864         (256 x KPAD fp16 = 36864)
//   P(q) = 73728 + q*9216  (64 x KPAD fp16 = 9216)
//   LS   = 92160           (64 f)
// ---------------------------------------------------------------------------
#define B_BUF(q) ((uint32_t)(q) * 36864u)
#define P_BUF(q) (73728u + (uint32_t)(q) * 9216u)
#define LS       92160u
#define ATTN_SMEM 92416

__global__ void __launch_bounds__(256, 2) attn_mma_kernel(const int* __restrict__ adj,
                                                          float* __restrict__ out) {
    extern __shared__ char smem[];
    const uint32_t sbase = smem_u32(smem);

    const int tid  = threadIdx.x;
    const int warp = tid >> 5;
    const int lane = tid & 31;
    const int b  = blockIdx.y;
    const int i0 = blockIdx.x * BI;

    const int wm = warp & 1;   // M block (32 rows)
    const int wn = warp >> 1;  // N block (64 cols)

    // softmax mapping: 4 threads per row, 16 j each
    const int sr = tid >> 2;
    const int sc = tid & 3;
    const float fi = g_f1[(size_t)b * NN + i0 + sr];
    const int* arow = adj + (size_t)b * NN * NN + (size_t)(i0 + sr) * NN + sc * 16;

    int4 pa[4];
    #pragma unroll
    for (int g = 0; g < 4; g++) pa[g] = *(const int4*)(arow + g * 4);   // tile 0

    // acc[mt][np][8]
    float acc[2][4][8];
    #pragma unroll
    for (int i = 0; i < 2; i++)
        #pragma unroll
        for (int j = 0; j < 4; j++)
            #pragma unroll
            for (int k = 0; k < 8; k++) acc[i][j][k] = 0.f;

    float lpart = 0.f;

    // per-thread cp.async source/dest for B rows (row n = tid)
    const char* srcB = (const char*)(g_WhT + ((size_t)(b * FOUT + tid)) * NN);
    const uint32_t dRow = (uint32_t)tid * (2 * KPAD);   // 144 B/row

    // A (P) ldsm offset within a P buffer
    const uint32_t aOff = 2u * (uint32_t)((wm * 32 + (lane & 15)) * KPAD + ((lane >> 4) << 3));
    // P store offset within a P buffer (32 B per thread)
    const uint32_t pOff = (uint32_t)(sr * (2 * KPAD) + sc * 32);

    // ---- prologue: start B(0) into buffer 0 (128 B per thread = 8 chunks) ----
    #pragma unroll
    for (int k = 0; k < 8; k++)
        CP_ASYNC16(sbase + B_BUF(0) + dRow + k * 16, srcB + k * 16);
    CP_COMMIT();

    for (int t = 0; t < NT; t++) {
        const int j0 = t * BJ;
        const uint32_t q = (uint32_t)(t & 1);

        // --- P tile: e -> exp -> fp16 into Pbuf[q] (16 j per thread) ---
        {
            float f2v[16];
            #pragma unroll
            for (int g = 0; g < 4; g++) {
                float4 fv = *(const float4*)(g_f2 + (size_t)b * NN + j0 + sc * 16 + g * 4);
                f2v[g * 4 + 0] = fv.x; f2v[g * 4 + 1] = fv.y;
                f2v[g * 4 + 2] = fv.z; f2v[g * 4 + 3] = fv.w;
            }
            int am[16] = {pa[0].x, pa[0].y, pa[0].z, pa[0].w,
                          pa[1].x, pa[1].y, pa[1].z, pa[1].w,
                          pa[2].x, pa[2].y, pa[2].z, pa[2].w,
                          pa[3].x, pa[3].y, pa[3].z, pa[3].w};
            union { __half2 h2[8]; uint4 u[2]; } ph;
            #pragma unroll
            for (int qq = 0; qq < 8; qq++) {
                float e0 = fi + f2v[2 * qq];
                float e1 = fi + f2v[2 * qq + 1];
                e0 = (e0 > 0.f) ? e0 : ALPHA_F * e0;
                e1 = (e1 > 0.f) ? e1 : ALPHA_F * e1;
                e0 = (am[2 * qq] == 0)     ? NEG_INF_F : e0;
                e1 = (am[2 * qq + 1] == 0) ? NEG_INF_F : e1;
                float p0 = __expf(e0);     // 0 when masked; |e|<=~7 otherwise
                float p1 = __expf(e1);
                lpart += p0 + p1;
                ph.h2[qq].x = __float2half(p0);
                ph.h2[qq].y = __float2half(p1);
            }
            *(uint4*)(smem + P_BUF(q) + pOff)      = ph.u[0];
            *(uint4*)(smem + P_BUF(q) + pOff + 16) = ph.u[1];
        }

        // prefetch adj(t+1) into regs (latency hidden by MMA phase)
        if (t + 1 < NT) {
            #pragma unroll
            for (int g = 0; g < 4; g++)
                pa[g] = *(const int4*)(arow + (j0 + BJ) + g * 4);
        }

        CP_WAIT0();          // own B(t) copies landed
        __syncthreads();     // all P/B(t) visible; all MMA(t-1) done

        // --- start B(t+1) into the opposite buffer (overlaps MMA below) ---
        if (t + 1 < NT) {
            const char* sB = srcB + (size_t)(j0 + BJ) * 2;
            const uint32_t bb = sbase + B_BUF(q ^ 1) + dRow;
            #pragma unroll
            for (int k = 0; k < 8; k++)
                CP_ASYNC16(bb + k * 16, sB + k * 16);
            CP_COMMIT();
        }

        // --- MMA phase on buffers q: 4 kc x (2 A-ldsm + 4 B-ldsm + 16 mma) ---
        const uint32_t aABase = sbase + P_BUF(q) + aOff;
        #pragma unroll
        for (int kc = 0; kc < 4; kc++) {
            uint32_t ah[2][4];
            #pragma unroll
            for (int mt = 0; mt < 2; mt++)
                ldsm4(ah[mt][0], ah[mt][1], ah[mt][2], ah[mt][3],
                      aABase + (uint32_t)(mt * 16 * KPAD * 2 + kc * 32));

            const int nbase = wn * 64 + (lane & 7) + ((lane >> 4) << 3);
            const int kcol  = kc * 16 + (((lane >> 3) & 1) << 3);
            #pragma unroll
            for (int np = 0; np < 4; np++) {
                uint32_t boff = 2u * (uint32_t)((nbase + np * 16) * KPAD + kcol);
                uint32_t b0, b1, b2, b3;
                ldsm4(b0, b1, b2, b3, sbase + B_BUF(q) + boff);
                #pragma unroll
                for (int mt = 0; mt < 2; mt++) {
                    mma16816h(acc[mt][np] + 0, ah[mt][0], ah[mt][1], ah[mt][2], ah[mt][3], b0, b1);
                    mma16816h(acc[mt][np] + 4, ah[mt][0], ah[mt][1], ah[mt][2], ah[mt][3], b2, b3);
                }
            }
        }
    }

    // --- l reduction across the 4-thread row group (consecutive lanes) ---
    float ls = lpart;
    ls += __shfl_xor_sync(0xffffffffu, ls, 1);
    ls += __shfl_xor_sync(0xffffffffu, ls, 2);
    float* l_s = (float*)(smem + LS);
    __syncthreads();
    if (sc == 0) l_s[sr] = ls;
    __syncthreads();

    // --- normalize + write (fp32, 8B stores; 32B contiguous per 4 lanes) ---
    float* outb = out + ((size_t)b * NN + i0) * FOUT;
    #pragma unroll
    for (int mt = 0; mt < 2; mt++) {
        const int r0 = wm * 32 + mt * 16 + (lane >> 2);
        const int r1 = r0 + 8;
        const float inv0 = 1.0f / l_s[r0];
        const float inv1 = 1.0f / l_s[r1];
        #pragma unroll
        for (int np = 0; np < 4; np++) {
            int c = wn * 64 + np * 16 + (lane & 3) * 2;
            *(float2*)&outb[(size_t)r0 * FOUT + c]     = make_float2(acc[mt][np][0] * inv0, acc[mt][np][1] * inv0);
            *(float2*)&outb[(size_t)r1 * FOUT + c]     = make_float2(acc[mt][np][2] * inv1, acc[mt][np][3] * inv1);
            *(float2*)&outb[(size_t)r0 * FOUT + c + 8] = make_float2(acc[mt][np][4] * inv0, acc[mt][np][5] * inv0);
            *(float2*)&outb[(size_t)r1 * FOUT + c + 8] = make_float2(acc[mt][np][6] * inv1, acc[mt][np][7] * inv1);
        }
    }
}

// ---------------------------------------------------------------------------
extern "C" void kernel_launch(void* const* d_in, const int* in_sizes, int n_in,
                              void* d_out, int out_size) {
    (void)in_sizes; (void)n_in; (void)out_size;
    const float* h   = (const float*)d_in[0];
    const int*   adj = (const int*)d_in[1];
    const float* W   = (const float*)d_in[2];
    const float* a   = (const float*)d_in[3];
    float* out = (float*)d_out;

    cudaFuncSetAttribute(attn_mma_kernel,
                         cudaFuncAttributeMaxDynamicSharedMemorySize, ATTN_SMEM);

    dim3 g1(FOUT / 64, (BATCH * NN) / 64);       // (4, 256)
    gemm_wh_kernel<<<g1, 256>>>(h, W);

    dim3 gt(NN / 64, FOUT / 64, BATCH);          // (32, 4, 8)
    transp_kernel<<<gt, 256>>>();

    fvec_kernel<<<(BATCH * NN * 32) / 256, 256>>>(a);  // one warp per row

    dim3 g3(NN / BI, BATCH);                     // (32, 8)
    attn_mma_kernel<<<g3, 256, ATTN_SMEM>>>(adj, out);
}